// round 15
// baseline (speedup 1.0000x reference)
#include <cuda_runtime.h>
#include <cuda_fp16.h>

// ============================================================================
// CfC Liquid Neural Network, B=256, T=1024. Round 14.
// Temporal wavefront pipeline: at tick t, warp-group G0 computes cell0 step t,
// G1 computes cell1 step t-1, G2 computes cell2 step t-2 — concurrently.
// One __syncthreads per tick + one named barrier per group (dots -> epilogue).
// Double-buffered (parity) z vectors carry state between ticks.
//  - fp16 weights (fp32 z / fp32 acc), half2(k,k+1) [k2][u]; FFMA2 dots (R11).
//  - 128 CTAs x 512 threads, 2 batch rows per CTA.
//  - cell1+cell2 weights smem-resident; cell0 streamed from L2.
//  - balanced per-thread segment partition, fixed act slots (zeroed once).
// ============================================================================

#define F0 128
#define U0 135
#define C0 263
#define CP0 264
#define UP0 136
#define F1 135
#define U1 89
#define C1 224
#define CP1 224
#define UP1 92
#define F2 89
#define U2 32
#define C2 121
#define CP2 128
#define UP2 32

#define L0_MAT (CP0*UP0)            // 35904 halves per mat
#define L1_MAT (CP1*UP1)            // 20608
#define L2_MAT (CP2*UP2)            // 4096
#define OFF_W0 0
#define OFF_W1 (3*L0_MAT)
#define OFF_W2 (OFF_W1 + 3*L1_MAT)
#define TOT_W  (OFF_W2 + 3*L2_MAT)

#define OFF_B0 0
#define OFF_B1 (3*UP0)
#define OFF_B2 (OFF_B1 + 3*UP1)
#define TOT_B  (OFF_B2 + 3*UP2)

#define W0_V4   (L0_MAT/8)          // 4488 uint4 stride between cell0 mats
#define W1_V4   (L1_MAT/8)          // 2576
#define W2_V4   (L2_MAT/8)          // 512

__device__ __align__(16) __half g_wh[TOT_W];
__device__ float g_b[TOT_B];

// ---- packed fp32x2 FMA: d = a*b + d ----
__device__ __forceinline__ void fma2(float2& d, const float2& a, const float2& b)
{
    unsigned long long& dv = reinterpret_cast<unsigned long long&>(d);
    asm("fma.rn.f32x2 %0, %1, %2, %0;"
        : "+l"(dv)
        : "l"(reinterpret_cast<const unsigned long long&>(a)),
          "l"(reinterpret_cast<const unsigned long long&>(b)));
}

// ---- fast activations (MUFU-based; saturate correctly at +-inf) ----
__device__ __forceinline__ float fast_tanh(float x)
{
    float e = __expf(2.f * x);
    return 1.f - __fdividef(2.f, e + 1.f);
}
__device__ __forceinline__ float fast_sigmoid(float x)
{
    return __fdividef(1.f, 1.f + __expf(-x));
}

// ---- Pack: half linear idx within mat = (k2*UP + u)*2 + r, k = 2*k2 + r ----
template<int C, int CP, int U, int UP>
__global__ void pack_kernel(int woff, int boff,
    const float* __restrict__ ff1w, const float* __restrict__ ff1b,
    const float* __restrict__ ff2w, const float* __restrict__ ff2b,
    const float* __restrict__ taw,  const float* __restrict__ tab,
    const float* __restrict__ tbw,  const float* __restrict__ tbb,
    const int*   __restrict__ mask)
{
    const int per = CP * UP;
    const int n = 3 * per;
    for (int idx = blockIdx.x * blockDim.x + threadIdx.x; idx < n;
         idx += gridDim.x * blockDim.x) {
        int mat = idx / per;
        int e = idx - mat * per;
        int r = e & 1;
        int t1 = e >> 1;
        int u = t1 % UP;
        int k2 = t1 / UP;
        int c = 2 * k2 + r;
        float v = 0.f;
        if (c < C && u < U) {
            int src = u * C + c;
            if (mat == 0)      v = ff1w[src] * (float)mask[src];
            else if (mat == 1) v = ff2w[src] * (float)mask[src];
            else               v = taw[src] + tbw[src];
        }
        g_wh[woff + idx] = __float2half_rn(v);
    }
    for (int idx = blockIdx.x * blockDim.x + threadIdx.x; idx < 3 * UP;
         idx += gridDim.x * blockDim.x) {
        int mat = idx / UP;
        int u = idx - mat * UP;
        float v = 0.f;
        if (u < U) v = (mat == 0) ? ff1b[u] : (mat == 1 ? ff2b[u] : (tab[u] + tbb[u]));
        g_b[boff + idx] = v;
    }
}

// ---- Dot core: 4 units x 2 rows over k4 range [kb, ke); float2 acc over k ----
template<int UP>
__device__ __forceinline__ void dot2(
    const uint4* __restrict__ wbase,
    const float4* __restrict__ za, const float4* __restrict__ zb,
    int wof, int kb, int ke, float2 acc[8])
{
    const uint4* wp = wbase + (size_t)(2 * kb) * (UP / 4) + wof;
#pragma unroll 4
    for (int k4 = kb; k4 < ke; ++k4) {
        uint4 wa = wp[0];
        uint4 wc = wp[UP / 4];
        wp += UP / 2;
        float4 va = za[k4];
        float4 vb = zb[k4];
        float2 a01 = make_float2(va.x, va.y), a23 = make_float2(va.z, va.w);
        float2 b01 = make_float2(vb.x, vb.y), b23 = make_float2(vb.z, vb.w);
        float2 w;
        w = __half22float2(*(const __half2*)&wa.x);
        fma2(acc[0], w, a01); fma2(acc[1], w, b01);
        w = __half22float2(*(const __half2*)&wa.y);
        fma2(acc[2], w, a01); fma2(acc[3], w, b01);
        w = __half22float2(*(const __half2*)&wa.z);
        fma2(acc[4], w, a01); fma2(acc[5], w, b01);
        w = __half22float2(*(const __half2*)&wa.w);
        fma2(acc[6], w, a01); fma2(acc[7], w, b01);
        w = __half22float2(*(const __half2*)&wc.x);
        fma2(acc[0], w, a23); fma2(acc[1], w, b23);
        w = __half22float2(*(const __half2*)&wc.y);
        fma2(acc[2], w, a23); fma2(acc[3], w, b23);
        w = __half22float2(*(const __half2*)&wc.z);
        fma2(acc[4], w, a23); fma2(acc[5], w, b23);
        w = __half22float2(*(const __half2*)&wc.w);
        fma2(acc[6], w, a23); fma2(acc[7], w, b23);
    }
}

// ---- per-thread segment descriptor (computed once) ----
struct SegT { int wof, aof, kb, ke, bof; };

// Balanced partition of (3*NUBm ublocks x K4 iters) over N threads.
// slot 0 of each ublock = straddling segment; slots 1.. = segments starting
// inside. SLOTS=5. Threads span at most 2 ublocks (iters/thread < K4).
__device__ void make_segs(int j, int N, int NUBm, int K4, int WST,
                          int bias_base, int UPb, SegT& A, SegT& B)
{
    int TOT = 3 * NUBm * K4;
    int gs = (int)(((long long)j * TOT) / N);
    int ge = (int)(((long long)(j + 1) * TOT) / N);
    int ubg = gs / K4;
    int kb = gs - ubg * K4;
    int end = (ubg + 1) * K4;
    int ke = (ge < end) ? (ge - ubg * K4) : K4;
    int jb = (int)(((long long)ubg * K4 * N + TOT - 1) / TOT);
    int slot = j - jb + 1;
    int mat = ubg / NUBm, ubl = ubg - mat * NUBm;
    A.wof = mat * WST + ubl;
    A.aof = (ubg * 5 + slot) * 8;
    A.kb = kb; A.ke = ke;
    A.bof = (kb == 0) ? (bias_base + mat * UPb + ubl * 4) : -1;
    if (ge > end) {
        int ub2 = ubg + 1;
        int m2 = ub2 / NUBm, ul2 = ub2 - m2 * NUBm;
        B.wof = m2 * WST + ul2;
        B.aof = (ub2 * 5 + 0) * 8;
        B.kb = 0; B.ke = ge - end;
        B.bof = bias_base + m2 * UPb + ul2 * 4;
    } else {
        B.wof = 0; B.aof = 0; B.kb = 0; B.ke = 0; B.bof = -1;
    }
}

template<int UP>
__device__ __forceinline__ void run_seg(
    const uint4* __restrict__ wbase, const float4* __restrict__ za,
    const float4* __restrict__ zb, const SegT& S,
    const float* __restrict__ sb_, float* __restrict__ actg)
{
    float2 acc[8];
    if (S.bof >= 0) {
        float4 bv = *(const float4*)(sb_ + S.bof);
        acc[0] = make_float2(bv.x, 0.f); acc[1] = make_float2(bv.x, 0.f);
        acc[2] = make_float2(bv.y, 0.f); acc[3] = make_float2(bv.y, 0.f);
        acc[4] = make_float2(bv.z, 0.f); acc[5] = make_float2(bv.z, 0.f);
        acc[6] = make_float2(bv.w, 0.f); acc[7] = make_float2(bv.w, 0.f);
    } else {
#pragma unroll
        for (int i = 0; i < 8; ++i) acc[i] = make_float2(0.f, 0.f);
    }
    dot2<UP>(wbase, za, zb, S.wof, S.kb, S.ke, acc);
    float* ap = actg + S.aof;
    *(float4*)ap       = make_float4(acc[0].x + acc[0].y, acc[2].x + acc[2].y,
                                     acc[4].x + acc[4].y, acc[6].x + acc[6].y);
    *(float4*)(ap + 4) = make_float4(acc[1].x + acc[1].y, acc[3].x + acc[3].y,
                                     acc[5].x + acc[5].y, acc[7].x + acc[7].y);
}

// ---- smem layout (byte offsets; all multiples of 16) ----
#define SB_W1   0                            // 123648
#define SB_W2   (SB_W1 + 3*L1_MAT*2)         // 123648 (+24576)
#define SB_B    (SB_W2 + 3*L2_MAT*2)         // 148224 (+3120)
#define SB_Z0   (SB_B + TOT_B*4)             // 151344 (+2*528*4 = 4224)
#define SB_Z1   (SB_Z0 + 2*2*CP0*4)          // 155568 (+3584)
#define SB_Z2   (SB_Z1 + 2*2*CP1*4)          // 159152 (+2048)
#define SB_A0   (SB_Z2 + 2*2*CP2*4)          // 161200 (+102*5*8*4 = 16320)
#define SB_A1   (SB_A0 + 102*5*8*4)          // 177520 (+11040)
#define SB_A2   (SB_A1 + 69*5*8*4)           // 188560 (+3840)
#define SB_TOT  (SB_A2 + 24*5*8*4)           // 192400 B

__global__ __launch_bounds__(512, 1)
void lnn_main(const float* __restrict__ x, float* __restrict__ out)
{
    extern __shared__ __align__(16) char smraw[];
    float* sb   = (float*)(smraw + SB_B);
    float* z0   = (float*)(smraw + SB_Z0);   // [parity][2 rows][264]
    float* z1   = (float*)(smraw + SB_Z1);   // [parity][2][224]
    float* z2   = (float*)(smraw + SB_Z2);   // [parity][2][128]
    float* act0 = (float*)(smraw + SB_A0);   // [102 ubg][5 slots][2 rows][4 u]
    float* act1 = (float*)(smraw + SB_A1);   // [69][5][2][4]
    float* act2 = (float*)(smraw + SB_A2);   // [24][5][2][4]
    const uint4* sW1v = (const uint4*)(smraw + SB_W1);
    const uint4* sW2v = (const uint4*)(smraw + SB_W2);
    const uint4* gw0  = (const uint4*)g_wh;  // OFF_W0 == 0

    const int tid = threadIdx.x;

    // ---- init: weights into smem, biases, zero z + act ----
    {
        const uint4* gsrc = (const uint4*)g_wh;
        uint4* d1 = (uint4*)(smraw + SB_W1);
        uint4* d2 = (uint4*)(smraw + SB_W2);
        for (int i = tid; i < 3 * W1_V4; i += 512) d1[i] = gsrc[OFF_W1 / 8 + i];
        for (int i = tid; i < 3 * W2_V4; i += 512) d2[i] = gsrc[OFF_W2 / 8 + i];
    }
    for (int i = tid; i < TOT_B; i += 512) sb[i] = g_b[i];
    {
        float* zz = (float*)(smraw + SB_Z0);
        const int nz = (SB_TOT - SB_Z0) / 4;
        for (int i = tid; i < nz; i += 512) zz[i] = 0.f;
    }

    // ---- per-thread segment descriptors ----
    SegT A, B;
    if (tid < 288)      make_segs(tid,       288, 34, 66, W0_V4, OFF_B0, UP0, A, B);
    else if (tid < 448) make_segs(tid - 288, 160, 23, 56, W1_V4, OFF_B1, UP1, A, B);
    else                make_segs(tid - 448,  64,  8, 32, W2_V4, OFF_B2, UP2, A, B);

    __syncthreads();

    const int b0 = blockIdx.x * 2;
    const float4* xv = (const float4*)x + (size_t)b0 * 1024 * 32;
    float4 xreg = make_float4(0.f, 0.f, 0.f, 0.f);
    if (tid >= 448) {
        int jj = tid - 448;
        int r = jj >> 5, xi = jj & 31;
        // x(0) into z0 parity 0
        ((float4*)z0)[r * 66 + xi] = xv[((size_t)r * 1024 + 0) * 32 + xi];
        xreg = xv[((size_t)r * 1024 + 1) * 32 + xi];   // x(1)
    }
    __syncthreads();

    for (int tick = 0; tick < 1026; ++tick) {
        const int p = tick & 1;
        const int q = 1 - p;

        if (tid < 288) {
            // ================= G0: cell0, step tick =================
            if (tick < 1024) {
                const float4* za = (const float4*)(z0 + p * 528);
                run_seg<UP0>(gw0, za, za + 66, A, sb, act0);
                if (B.ke) run_seg<UP0>(gw0, za, za + 66, B, sb, act0);
            }
            asm volatile("bar.sync 1, 288;" ::: "memory");
            if (tick < 1024 && tid < 270) {
                int u = tid >> 1, r = tid & 1;
                int ubl = u >> 2, c = u & 3;
                float f1 = 0.f, f2 = 0.f, tt = 0.f;
#pragma unroll
                for (int s = 0; s < 5; ++s) {
                    f1 += act0[((0 * 34 + ubl) * 5 + s) * 8 + r * 4 + c];
                    f2 += act0[((1 * 34 + ubl) * 5 + s) * 8 + r * 4 + c];
                    tt += act0[((2 * 34 + ubl) * 5 + s) * 8 + r * 4 + c];
                }
                f1 = fast_tanh(f1); f2 = fast_tanh(f2);
                float s = fast_sigmoid(tt);
                float h = f1 + s * (f2 - f1);
                z0[q * 528 + r * 264 + 128 + u] = h;   // self-recurrence
                z1[q * 448 + r * 224 + u]       = h;   // cell1 input
            }
        } else if (tid < 448) {
            // ================= G1: cell1, step tick-1 =================
            const int jj = tid - 288;
            const bool on = (tick >= 1) && (tick <= 1024);
            if (on) {
                const float4* za = (const float4*)(z1 + p * 448);
                run_seg<UP1>(sW1v, za, za + 56, A, sb, act1);
                if (B.ke) run_seg<UP1>(sW1v, za, za + 56, B, sb, act1);
            }
            asm volatile("bar.sync 2, 160;" ::: "memory");
            if (on) {
                for (int i = jj; i < 178; i += 160) {
                    int u = i >> 1, r = i & 1;
                    int ubl = u >> 2, c = u & 3;
                    float f1 = 0.f, f2 = 0.f, tt = 0.f;
#pragma unroll
                    for (int s = 0; s < 5; ++s) {
                        f1 += act1[((0 * 23 + ubl) * 5 + s) * 8 + r * 4 + c];
                        f2 += act1[((1 * 23 + ubl) * 5 + s) * 8 + r * 4 + c];
                        tt += act1[((2 * 23 + ubl) * 5 + s) * 8 + r * 4 + c];
                    }
                    f1 = fast_tanh(f1); f2 = fast_tanh(f2);
                    float s = fast_sigmoid(tt);
                    float h = f1 + s * (f2 - f1);
                    z1[q * 448 + r * 224 + 135 + u] = h;   // self-recurrence
                    z2[q * 256 + r * 128 + u]       = h;   // cell2 input
                }
            }
        } else {
            // ======== G2: cell2 step tick-2, x prefetch, out store ========
            const int jj = tid - 448;
            const int r = jj >> 5, xi = jj & 31;
            if (tick <= 1022)
                ((float4*)(z0 + q * 528))[r * 66 + xi] = xreg;  // x(tick+1)
            const bool on = (tick >= 2);
            if (on) {
                const float4* za = (const float4*)(z2 + p * 256);
                run_seg<UP2>(sW2v, za, za + 32, A, sb, act2);
                if (B.ke) run_seg<UP2>(sW2v, za, za + 32, B, sb, act2);
            }
            asm volatile("bar.sync 3, 64;" ::: "memory");
            if (tick <= 1022) {
                int tn = (tick + 2 < 1024) ? tick + 2 : 1023;
                xreg = xv[((size_t)r * 1024 + tn) * 32 + xi];
            }
            if (on) {
                int u = jj >> 1, rr = jj & 1;
                int ubl = u >> 2, c = u & 3;
                float f1 = 0.f, f2 = 0.f, tt = 0.f;
#pragma unroll
                for (int s = 0; s < 5; ++s) {
                    f1 += act2[((0 * 8 + ubl) * 5 + s) * 8 + rr * 4 + c];
                    f2 += act2[((1 * 8 + ubl) * 5 + s) * 8 + rr * 4 + c];
                    tt += act2[((2 * 8 + ubl) * 5 + s) * 8 + rr * 4 + c];
                }
                f1 = fast_tanh(f1); f2 = fast_tanh(f2);
                float s = fast_sigmoid(tt);
                float h = f1 + s * (f2 - f1);
                z2[q * 256 + rr * 128 + 89 + u] = h;   // self-recurrence
                out[(((size_t)(b0 + rr)) * 1024 + (tick - 2)) * 32 + u] = h;
            }
        }
        __syncthreads();
    }
}

// ---- fc head applied in place over out[256*1024][32] ----
__global__ __launch_bounds__(256)
void fc_kernel(float* __restrict__ out, const float* __restrict__ fcw,
               const float* __restrict__ fcb)
{
    __shared__ float w[1024];
    __shared__ float b[32];
    int tid = threadIdx.x;
    for (int i = tid; i < 1024; i += 256) w[i] = fcw[i];
    if (tid < 32) b[tid] = fcb[tid];
    __syncthreads();

    size_t pos = (size_t)blockIdx.x * 256 + tid;
    float4* p = reinterpret_cast<float4*>(out) + pos * 8;
    float h[32];
    float4 v[8];
#pragma unroll
    for (int i = 0; i < 8; ++i) v[i] = p[i];
#pragma unroll
    for (int i = 0; i < 8; ++i) {
        h[4 * i + 0] = v[i].x; h[4 * i + 1] = v[i].y;
        h[4 * i + 2] = v[i].z; h[4 * i + 3] = v[i].w;
    }
#pragma unroll
    for (int i = 0; i < 8; ++i) {
        float y[4];
#pragma unroll
        for (int j = 0; j < 4; ++j) {
            int o = 4 * i + j;
            float acc = b[o];
#pragma unroll
            for (int u = 0; u < 32; ++u) acc = fmaf(w[o * 32 + u], h[u], acc);
            y[j] = acc;
        }
        p[i] = make_float4(y[0], y[1], y[2], y[3]);
    }
}

// ============================================================================
extern "C" void kernel_launch(void* const* d_in, const int* in_sizes, int n_in,
                              void* d_out, int out_size)
{
    (void)n_in; (void)out_size;
    int base[3], mi[3], fwi, fbi;
    if (in_sizes[9] == U0 * C0) {          // interleaved dict order
        base[0] = 1;  mi[0] = 9;
        base[1] = 10; mi[1] = 18;
        base[2] = 19; mi[2] = 27;
        fwi = 28; fbi = 29;
    } else {                                // signature order
        base[0] = 1; base[1] = 9; base[2] = 17;
        fwi = 25; fbi = 26;
        mi[0] = 27; mi[1] = 28; mi[2] = 29;
    }

    const float* xin = (const float*)d_in[0];
    const float* fcw = (const float*)d_in[fwi];
    const float* fcb = (const float*)d_in[fbi];

#define LPTRS(l) \
    (const float*)d_in[base[l]+0], (const float*)d_in[base[l]+1], \
    (const float*)d_in[base[l]+2], (const float*)d_in[base[l]+3], \
    (const float*)d_in[base[l]+4], (const float*)d_in[base[l]+5], \
    (const float*)d_in[base[l]+6], (const float*)d_in[base[l]+7], \
    (const int*)d_in[mi[l]]

    pack_kernel<C0, CP0, U0, UP0><<<(3 * L0_MAT + 255) / 256, 256>>>(OFF_W0, OFF_B0, LPTRS(0));
    pack_kernel<C1, CP1, U1, UP1><<<(3 * L1_MAT + 255) / 256, 256>>>(OFF_W1, OFF_B1, LPTRS(1));
    pack_kernel<C2, CP2, U2, UP2><<<(3 * L2_MAT + 255) / 256, 256>>>(OFF_W2, OFF_B2, LPTRS(2));
#undef LPTRS

    static_assert(SB_TOT <= 232448, "smem over budget");
    cudaFuncSetAttribute(lnn_main, cudaFuncAttributeMaxDynamicSharedMemorySize,
                         SB_TOT);
    lnn_main<<<128, 512, SB_TOT>>>(xin, (float*)d_out);
    fc_kernel<<<1024, 256>>>((float*)d_out, fcw, fcb);
}

// round 16
// speedup vs baseline: 3.0372x; 3.0372x over previous
#include <cuda_runtime.h>
#include <cuda_fp16.h>

// ============================================================================
// CfC Liquid Neural Network, B=256, T=1024. Round 15 = Round 11 (best known)
// + software-pipelined weight prefetch in the cell0 (L2-streamed) dot loop.
//  - fp16 weights (fp32 z / fp32 acc) packed half2 (k,k+1) [k2][u]; FFMA2.
//  - 128 CTAs x 512 threads, 2 batch rows per CTA, 1024-step recurrence.
//  - cell1+cell2 weights smem-resident; cell0 streamed from L2 (KS0=5).
//  - fast __expf activations; x-store fused into epi0; 6 barriers/step.
//  - fc head applied by a separate elementwise kernel.
// ============================================================================

#define F0 128
#define U0 135
#define C0 263
#define CP0 264
#define UP0 136
#define F1 135
#define U1 89
#define C1 224
#define CP1 224
#define UP1 92
#define F2 89
#define U2 32
#define C2 121
#define CP2 128
#define UP2 32

#define L0_MAT (CP0*UP0)            // 35904 halves per mat
#define L1_MAT (CP1*UP1)            // 20608
#define L2_MAT (CP2*UP2)            // 4096
#define OFF_W0 0
#define OFF_W1 (3*L0_MAT)
#define OFF_W2 (OFF_W1 + 3*L1_MAT)
#define TOT_W  (OFF_W2 + 3*L2_MAT)

#define OFF_B0 0
#define OFF_B1 (3*UP0)
#define OFF_B2 (OFF_B1 + 3*UP1)
#define TOT_B  (OFF_B2 + 3*UP2)

__device__ __align__(16) __half g_wh[TOT_W];
__device__ float g_b[TOT_B];

// ---- packed fp32x2 FMA: d = a*b + d (one SASS FFMA2 issue) ----
__device__ __forceinline__ void fma2(float2& d, const float2& a, const float2& b)
{
    unsigned long long& dv = reinterpret_cast<unsigned long long&>(d);
    asm("fma.rn.f32x2 %0, %1, %2, %0;"
        : "+l"(dv)
        : "l"(reinterpret_cast<const unsigned long long&>(a)),
          "l"(reinterpret_cast<const unsigned long long&>(b)));
}

// ---- fast activations (MUFU-based; saturate correctly at +-inf) ----
__device__ __forceinline__ float fast_tanh(float x)
{
    float e = __expf(2.f * x);
    return 1.f - __fdividef(2.f, e + 1.f);
}
__device__ __forceinline__ float fast_sigmoid(float x)
{
    return __fdividef(1.f, 1.f + __expf(-x));
}

// ---- Pack: half linear idx within mat = (k2*UP + u)*2 + r, k = 2*k2 + r ----
template<int C, int CP, int U, int UP>
__global__ void pack_kernel(int woff, int boff,
    const float* __restrict__ ff1w, const float* __restrict__ ff1b,
    const float* __restrict__ ff2w, const float* __restrict__ ff2b,
    const float* __restrict__ taw,  const float* __restrict__ tab,
    const float* __restrict__ tbw,  const float* __restrict__ tbb,
    const int*   __restrict__ mask)
{
    const int per = CP * UP;
    const int n = 3 * per;
    for (int idx = blockIdx.x * blockDim.x + threadIdx.x; idx < n;
         idx += gridDim.x * blockDim.x) {
        int mat = idx / per;
        int e = idx - mat * per;
        int r = e & 1;
        int t1 = e >> 1;
        int u = t1 % UP;
        int k2 = t1 / UP;
        int c = 2 * k2 + r;
        float v = 0.f;
        if (c < C && u < U) {
            int src = u * C + c;
            if (mat == 0)      v = ff1w[src] * (float)mask[src];
            else if (mat == 1) v = ff2w[src] * (float)mask[src];
            else               v = taw[src] + tbw[src];
        }
        g_wh[woff + idx] = __float2half_rn(v);
    }
    for (int idx = blockIdx.x * blockDim.x + threadIdx.x; idx < 3 * UP;
         idx += gridDim.x * blockDim.x) {
        int mat = idx / UP;
        int u = idx - mat * UP;
        float v = 0.f;
        if (u < U) v = (mat == 0) ? ff1b[u] : (mat == 1 ? ff2b[u] : (tab[u] + tbb[u]));
        g_b[boff + idx] = v;
    }
}

// ---- FMA block shared by both dot variants ----
__device__ __forceinline__ void fma_block(
    const uint4& wa, const uint4& wc, const float4& va, const float4& vb,
    float2 acc[8])
{
    float2 a01 = make_float2(va.x, va.y), a23 = make_float2(va.z, va.w);
    float2 b01 = make_float2(vb.x, vb.y), b23 = make_float2(vb.z, vb.w);
    float2 w;
    w = __half22float2(*(const __half2*)&wa.x);
    fma2(acc[0], w, a01); fma2(acc[1], w, b01);
    w = __half22float2(*(const __half2*)&wa.y);
    fma2(acc[2], w, a01); fma2(acc[3], w, b01);
    w = __half22float2(*(const __half2*)&wa.z);
    fma2(acc[4], w, a01); fma2(acc[5], w, b01);
    w = __half22float2(*(const __half2*)&wa.w);
    fma2(acc[6], w, a01); fma2(acc[7], w, b01);
    w = __half22float2(*(const __half2*)&wc.x);
    fma2(acc[0], w, a23); fma2(acc[1], w, b23);
    w = __half22float2(*(const __half2*)&wc.y);
    fma2(acc[2], w, a23); fma2(acc[3], w, b23);
    w = __half22float2(*(const __half2*)&wc.z);
    fma2(acc[4], w, a23); fma2(acc[5], w, b23);
    w = __half22float2(*(const __half2*)&wc.w);
    fma2(acc[6], w, a23); fma2(acc[7], w, b23);
}

// ---- Dot task (smem weights): plain loop ----
template<int UP>
__device__ __forceinline__ void dot2(
    const uint4* __restrict__ wbase,
    const float4* __restrict__ za, const float4* __restrict__ zb,
    int ub, int kb, int ke, float2 acc[8])
{
    const uint4* wp = wbase + (size_t)(2 * kb) * (UP / 4) + ub;
#pragma unroll 4
    for (int k4 = kb; k4 < ke; ++k4) {
        uint4 wa = wp[0];
        uint4 wc = wp[UP / 4];
        wp += UP / 2;
        fma_block(wa, wc, za[k4], zb[k4], acc);
    }
}

// ---- Dot task (L2-streamed weights): software-pipelined prefetch ----
template<int UP>
__device__ __forceinline__ void dot2g(
    const uint4* __restrict__ wbase,
    const float4* __restrict__ za, const float4* __restrict__ zb,
    int ub, int kb, int ke, float2 acc[8])
{
    const uint4* wp = wbase + (size_t)(2 * kb) * (UP / 4) + ub;
    uint4 wa = wp[0];
    uint4 wc = wp[UP / 4];
#pragma unroll 4
    for (int k4 = kb; k4 < ke - 1; ++k4) {
        wp += UP / 2;
        uint4 na = wp[0];          // issued BEFORE the FMA block: overlap
        uint4 nc = wp[UP / 4];
        fma_block(wa, wc, za[k4], zb[k4], acc);
        wa = na; wc = nc;
    }
    fma_block(wa, wc, za[ke - 1], zb[ke - 1], acc);
}

// ---- smem layout (byte offsets; all multiples of 16) ----
#define SB_W1   0                            // 3*L1_MAT halves
#define SB_W2   (SB_W1 + 3*L1_MAT*2)
#define SB_B    (SB_W2 + 3*L2_MAT*2)
#define SB_Z0   (SB_B + TOT_B*4)
#define SB_Z1   (SB_Z0 + 2*CP0*4)
#define SB_Z2   (SB_Z1 + 2*CP1*4)
#define SB_ACT  (SB_Z2 + 2*CP2*4)
#define SB_TOT  (SB_ACT + 3*5*2*UP0*4)       // 172592 B

#define KS0 5
#define KS1 7
#define KS2 16

__global__ __launch_bounds__(512, 1)
void lnn_main(const float* __restrict__ x, float* __restrict__ out)
{
    extern __shared__ __align__(16) char smraw[];
    __half* sW1 = (__half*)(smraw + SB_W1);
    __half* sW2 = (__half*)(smraw + SB_W2);
    float*  sb  = (float*)(smraw + SB_B);
    float*  z0  = (float*)(smraw + SB_Z0);
    float*  z1  = (float*)(smraw + SB_Z1);
    float*  z2  = (float*)(smraw + SB_Z2);
    float*  act = (float*)(smraw + SB_ACT);
    const uint4* sW1v = (const uint4*)sW1;
    const uint4* sW2v = (const uint4*)sW2;
    const uint4* gw0  = (const uint4*)g_wh;      // OFF_W0 == 0
    float4* z0v = (float4*)z0;
    const float4* z1v = (const float4*)z1;
    const float4* z2v = (const float4*)z2;

    const int tid = threadIdx.x;

    // Fill smem caches
    {
        const uint4* gsrc = (const uint4*)g_wh;
        uint4* d1 = (uint4*)sW1;
        uint4* d2 = (uint4*)sW2;
        for (int i = tid; i < 3 * L1_MAT / 8; i += 512) d1[i] = gsrc[OFF_W1 / 8 + i];
        for (int i = tid; i < 3 * L2_MAT / 8; i += 512) d2[i] = gsrc[OFF_W2 / 8 + i];
    }
    for (int i = tid; i < TOT_B; i += 512) sb[i] = g_b[i];
    for (int i = tid; i < 2 * CP0; i += 512) z0[i] = 0.f;
    for (int i = tid; i < 2 * CP1; i += 512) z1[i] = 0.f;
    for (int i = tid; i < 2 * CP2; i += 512) z2[i] = 0.f;
    __syncthreads();

    const int b0 = blockIdx.x * 2;
    const float4* xv = (const float4*)x + (size_t)b0 * 1024 * 32;
    // x-prefetch threads: 448..511 (disjoint from epi0's 0..269)
    const int xr = (tid - 448) >> 5, xi = (tid - 448) & 31;

    float4 xreg = make_float4(0.f, 0.f, 0.f, 0.f);
    if (tid >= 448)
        z0v[xr * (CP0 / 4) + xi] = xv[((size_t)xr * 1024 + 0) * 32 + xi];
    __syncthreads();
    if (tid >= 448) xreg = xv[((size_t)xr * 1024 + 1) * 32 + xi];

    for (int t = 0; t < 1024; ++t) {
        // ======== Cell 0 (L2-streamed, pipelined): 3 x 34 x 5 = 510 tasks
        if (tid < 510) {
            int ub = tid % 34, q = tid / 34;
            int ks = q % KS0, mat = q / KS0;
            int u0 = 4 * ub;
            float2 acc[8];
#pragma unroll
            for (int u = 0; u < 4; ++u) {
                float bv = (ks == 0) ? sb[OFF_B0 + mat * UP0 + u0 + u] : 0.f;
                acc[2 * u]     = make_float2(bv, 0.f);
                acc[2 * u + 1] = make_float2(bv, 0.f);
            }
            int kb = (ks * 66) / KS0, ke = ((ks + 1) * 66) / KS0;
            dot2g<UP0>(gw0 + mat * (L0_MAT / 8), z0v, z0v + CP0 / 4, ub, kb, ke, acc);
            float* ap = act + ((mat * KS0 + ks) * 2) * UP0 + u0;
            *(float4*)ap         = make_float4(acc[0].x + acc[0].y, acc[2].x + acc[2].y,
                                               acc[4].x + acc[4].y, acc[6].x + acc[6].y);
            *(float4*)(ap + UP0) = make_float4(acc[1].x + acc[1].y, acc[3].x + acc[3].y,
                                               acc[5].x + acc[5].y, acc[7].x + acc[7].y);
        }
        __syncthreads();

        // ======== epi0 (270 thr) fused with x_{t+1} store (threads 448+)
        if (tid < 270) {
            int u = tid >> 1, r = tid & 1;
            float f1 = 0.f, f2 = 0.f, tt = 0.f;
#pragma unroll
            for (int ks = 0; ks < KS0; ++ks) {
                f1 += act[((0 * KS0 + ks) * 2 + r) * UP0 + u];
                f2 += act[((1 * KS0 + ks) * 2 + r) * UP0 + u];
                tt += act[((2 * KS0 + ks) * 2 + r) * UP0 + u];
            }
            f1 = fast_tanh(f1); f2 = fast_tanh(f2);
            float s = fast_sigmoid(tt);
            float h = f1 + s * (f2 - f1);
            z0[r * CP0 + F0 + u] = h;
            z1[r * CP1 + u]      = h;
        } else if (tid >= 448) {
            z0v[xr * (CP0 / 4) + xi] = xreg;   // x_{t+1} into z0 (x-slice dead)
        }
        __syncthreads();
        if (tid >= 448) {
            int tn = (t + 2 < 1024) ? t + 2 : 1023;
            xreg = xv[((size_t)xr * 1024 + tn) * 32 + xi];
        }

        // ======== Cell 1 (smem fp16): 3 mats x 23 ublk x 7 ks = 483 tasks
        if (tid < 483) {
            int ub = tid % 23, q = tid / 23;
            int ks = q % KS1, mat = q / KS1;
            int u0 = 4 * ub;
            float2 acc[8];
#pragma unroll
            for (int u = 0; u < 4; ++u) {
                float bv = (ks == 0) ? sb[OFF_B1 + mat * UP1 + u0 + u] : 0.f;
                acc[2 * u]     = make_float2(bv, 0.f);
                acc[2 * u + 1] = make_float2(bv, 0.f);
            }
            int kb = ks * 8, ke = kb + 8;
            dot2<UP1>(sW1v + mat * (L1_MAT / 8), z1v, z1v + CP1 / 4, ub, kb, ke, acc);
            float* ap = act + ((mat * KS1 + ks) * 2) * UP1 + u0;
            *(float4*)ap         = make_float4(acc[0].x + acc[0].y, acc[2].x + acc[2].y,
                                               acc[4].x + acc[4].y, acc[6].x + acc[6].y);
            *(float4*)(ap + UP1) = make_float4(acc[1].x + acc[1].y, acc[3].x + acc[3].y,
                                               acc[5].x + acc[5].y, acc[7].x + acc[7].y);
        }
        __syncthreads();
        if (tid < 178) {
            int u = tid >> 1, r = tid & 1;
            float f1 = 0.f, f2 = 0.f, tt = 0.f;
#pragma unroll
            for (int ks = 0; ks < KS1; ++ks) {
                f1 += act[((0 * KS1 + ks) * 2 + r) * UP1 + u];
                f2 += act[((1 * KS1 + ks) * 2 + r) * UP1 + u];
                tt += act[((2 * KS1 + ks) * 2 + r) * UP1 + u];
            }
            f1 = fast_tanh(f1); f2 = fast_tanh(f2);
            float s = fast_sigmoid(tt);
            float h = f1 + s * (f2 - f1);
            z1[r * CP1 + F1 + u] = h;
            z2[r * CP2 + u]      = h;
        }
        __syncthreads();

        // ======== Cell 2 (smem fp16): 3 mats x 8 ublk x 16 ks = 384 tasks
        if (tid < 384) {
            int ub = tid & 7, q = tid >> 3;
            int ks = q & 15, mat = q >> 4;
            int u0 = 4 * ub;
            float2 acc[8];
#pragma unroll
            for (int u = 0; u < 4; ++u) {
                float bv = (ks == 0) ? sb[OFF_B2 + mat * UP2 + u0 + u] : 0.f;
                acc[2 * u]     = make_float2(bv, 0.f);
                acc[2 * u + 1] = make_float2(bv, 0.f);
            }
            int kb = ks * 2, ke = kb + 2;
            dot2<UP2>(sW2v + mat * (L2_MAT / 8), z2v, z2v + CP2 / 4, ub, kb, ke, acc);
            float* ap = act + ((mat * KS2 + ks) * 2) * UP2 + u0;
            *(float4*)ap         = make_float4(acc[0].x + acc[0].y, acc[2].x + acc[2].y,
                                               acc[4].x + acc[4].y, acc[6].x + acc[6].y);
            *(float4*)(ap + UP2) = make_float4(acc[1].x + acc[1].y, acc[3].x + acc[3].y,
                                               acc[5].x + acc[5].y, acc[7].x + acc[7].y);
        }
        __syncthreads();
        if (tid < 64) {
            int u = tid >> 1, r = tid & 1;
            float f1 = 0.f, f2 = 0.f, tt = 0.f;
#pragma unroll
            for (int ks = 0; ks < KS2; ++ks) {
                f1 += act[((0 * KS2 + ks) * 2 + r) * UP2 + u];
                f2 += act[((1 * KS2 + ks) * 2 + r) * UP2 + u];
                tt += act[((2 * KS2 + ks) * 2 + r) * UP2 + u];
            }
            f1 = fast_tanh(f1); f2 = fast_tanh(f2);
            float s = fast_sigmoid(tt);
            float h = f1 + s * (f2 - f1);
            z2[r * CP2 + F2 + u] = h;
            out[(((size_t)(b0 + r)) * 1024 + t) * 32 + u] = h;
        }
        __syncthreads();
    }
}

// ---- fc head applied in place over out[256*1024][32] ----
__global__ __launch_bounds__(256)
void fc_kernel(float* __restrict__ out, const float* __restrict__ fcw,
               const float* __restrict__ fcb)
{
    __shared__ float w[1024];
    __shared__ float b[32];
    int tid = threadIdx.x;
    for (int i = tid; i < 1024; i += 256) w[i] = fcw[i];
    if (tid < 32) b[tid] = fcb[tid];
    __syncthreads();

    size_t pos = (size_t)blockIdx.x * 256 + tid;
    float4* p = reinterpret_cast<float4*>(out) + pos * 8;
    float h[32];
    float4 v[8];
#pragma unroll
    for (int i = 0; i < 8; ++i) v[i] = p[i];
#pragma unroll
    for (int i = 0; i < 8; ++i) {
        h[4 * i + 0] = v[i].x; h[4 * i + 1] = v[i].y;
        h[4 * i + 2] = v[i].z; h[4 * i + 3] = v[i].w;
    }
#pragma unroll
    for (int i = 0; i < 8; ++i) {
        float y[4];
#pragma unroll
        for (int j = 0; j < 4; ++j) {
            int o = 4 * i + j;
            float acc = b[o];
#pragma unroll
            for (int u = 0; u < 32; ++u) acc = fmaf(w[o * 32 + u], h[u], acc);
            y[j] = acc;
        }
        p[i] = make_float4(y[0], y[1], y[2], y[3]);
    }
}

// ============================================================================
extern "C" void kernel_launch(void* const* d_in, const int* in_sizes, int n_in,
                              void* d_out, int out_size)
{
    (void)n_in; (void)out_size;
    int base[3], mi[3], fwi, fbi;
    if (in_sizes[9] == U0 * C0) {          // interleaved dict order
        base[0] = 1;  mi[0] = 9;
        base[1] = 10; mi[1] = 18;
        base[2] = 19; mi[2] = 27;
        fwi = 28; fbi = 29;
    } else {                                // signature order
        base[0] = 1; base[1] = 9; base[2] = 17;
        fwi = 25; fbi = 26;
        mi[0] = 27; mi[1] = 28; mi[2] = 29;
    }

    const float* xin = (const float*)d_in[0];
    const float* fcw = (const float*)d_in[fwi];
    const float* fcb = (const float*)d_in[fbi];

#define LPTRS(l) \
    (const float*)d_in[base[l]+0], (const float*)d_in[base[l]+1], \
    (const float*)d_in[base[l]+2], (const float*)d_in[base[l]+3], \
    (const float*)d_in[base[l]+4], (const float*)d_in[base[l]+5], \
    (const float*)d_in[base[l]+6], (const float*)d_in[base[l]+7], \
    (const int*)d_in[mi[l]]

    pack_kernel<C0, CP0, U0, UP0><<<(3 * L0_MAT + 255) / 256, 256>>>(OFF_W0, OFF_B0, LPTRS(0));
    pack_kernel<C1, CP1, U1, UP1><<<(3 * L1_MAT + 255) / 256, 256>>>(OFF_W1, OFF_B1, LPTRS(1));
    pack_kernel<C2, CP2, U2, UP2><<<(3 * L2_MAT + 255) / 256, 256>>>(OFF_W2, OFF_B2, LPTRS(2));
#undef LPTRS

    static_assert(SB_TOT <= 232448, "smem over budget");
    cudaFuncSetAttribute(lnn_main, cudaFuncAttributeMaxDynamicSharedMemorySize,
                         SB_TOT);
    lnn_main<<<128, 512, SB_TOT>>>(xin, (float*)d_out);
    fc_kernel<<<1024, 256>>>((float*)d_out, fcw, fcb);
}